// round 13
// baseline (speedup 1.0000x reference)
#include <cuda_runtime.h>
#include <cuda_bf16.h>
#include <cstdint>
#include <math.h>

// Problem constants
#define N_LIG 1024
#define N_PROT 8192
#define N_ALL 9216
#define KNN 48
#define NEDGE (N_LIG*KNN)          // 49152
#define HID 256
#define FEAT 32
#define DEPTH 5
#define FIN 40

__constant__ float c_freqs[6] = {
    0.4188790204786391f, 1.6755160819145564f, 6.702064327658226f,
    26.808257310632902f, 107.23302924253161f, 428.93211697012644f
};

typedef __nv_bfloat16 bf16;

// ---------------- device scratch ----------------
__device__ float g_x[N_ALL*3];
__device__ float g_h[N_ALL*HID];
__device__ float g_m2[NEDGE*HID];
__device__ int   g_col[NEDGE];
__device__ float g_emb0[NEDGE*12];
__device__ float g_cdiff[NEDGE*3];
__device__ float g_part[NEDGE*2];    // att-gate partial dots (2 halves)
__device__ float g_spart[NEDGE*2];   // coord-scalar partial dots (2 halves)

// bf16 split (hi/lo) arrays
__device__ bf16 g_feats_h[N_ALL*64],  g_feats_l[N_ALL*64];
__device__ bf16 g_h_h[N_ALL*HID],     g_h_l[N_ALL*HID];
__device__ bf16 g_u_h[N_ALL*HID],     g_u_l[N_ALL*HID];
__device__ bf16 g_agg_h[N_LIG*HID],   g_agg_l[N_LIG*HID];
__device__ bf16 g_ea_h[NEDGE*32],     g_ea_l[NEDGE*32];
__device__ bf16 g_m1_h[NEDGE*HID],    g_m1_l[NEDGE*HID];
// transposed split weights [layer][N][ldw]
__device__ bf16 g_we1_h[DEPTH*HID*544], g_we1_l[DEPTH*HID*544];
__device__ bf16 g_we2_h[DEPTH*HID*256], g_we2_l[DEPTH*HID*256];
__device__ bf16 g_wn1_h[DEPTH*HID*512], g_wn1_l[DEPTH*HID*512];
__device__ bf16 g_wn2_h[DEPTH*HID*256], g_wn2_l[DEPTH*HID*256];
__device__ bf16 g_wc1_h[DEPTH*HID*544], g_wc1_l[DEPTH*HID*544];
__device__ bf16 g_wc2_h[DEPTH*HID*256], g_wc2_l[DEPTH*HID*256];
__device__ bf16 g_win_h[HID*64],        g_win_l[HID*64];

__device__ __forceinline__ void split2(float v, bf16& h, bf16& l) {
    h = __float2bfloat16_rn(v);
    l = __float2bfloat16_rn(v - __bfloat162float(h));
}

// ---------------- weight convert+transpose+split ----------------
__global__ void wsplit_k(const float* __restrict__ W, bf16* __restrict__ hi,
                         bf16* __restrict__ lo, int K, int N, int ldw, int total)
{
    int idx = blockIdx.x*blockDim.x + threadIdx.x;
    if (idx >= total) return;
    int k = idx % ldw;
    int rem = idx / ldw;
    int n = rem % N;
    int l = rem / N;
    float v = (k < K) ? W[((size_t)l*K + k)*N + n] : 0.f;
    bf16 h, lw; split2(v, h, lw);
    hi[idx] = h; lo[idx] = lw;
}

// ---------------- embed ----------------
__global__ void embed_k(const float* __restrict__ pp, const int* __restrict__ pe,
                        const int* __restrict__ pa, const int* __restrict__ pb,
                        const float* __restrict__ xt, const float* __restrict__ xf,
                        const int* __restrict__ tt, const float* __restrict__ wt,
                        const float* __restrict__ we, const float* __restrict__ wa,
                        const float* __restrict__ wb)
{
    int i = blockIdx.x*blockDim.x + threadIdx.x;
    if (i >= N_ALL) return;
    float f[64];
    #pragma unroll
    for (int k=0;k<64;k++) f[k]=0.f;
    if (i < N_LIG) {
        #pragma unroll
        for (int k=0;k<32;k++) f[k] = xf[i*32+k];
        int t = tt[i];
        #pragma unroll
        for (int k=0;k<8;k++) f[32+k] = wt[t*8+k];
        g_x[i*3+0]=xt[i*3+0]; g_x[i*3+1]=xt[i*3+1]; g_x[i*3+2]=xt[i*3+2];
    } else {
        int p = i - N_LIG;
        int e = pe[p], a = pa[p], b = pb[p];
        #pragma unroll
        for (int k=0;k<16;k++) f[k]    = we[e*16+k];
        #pragma unroll
        for (int k=0;k<16;k++) f[16+k] = wa[a*16+k];
        #pragma unroll
        for (int k=0;k<8;k++)  f[32+k] = wb[b*8+k];
        g_x[i*3+0]=pp[p*3+0]; g_x[i*3+1]=pp[p*3+1]; g_x[i*3+2]=pp[p*3+2];
    }
    #pragma unroll
    for (int k=0;k<64;k++) {
        bf16 h,l; split2(f[k], h, l);
        g_feats_h[i*64+k]=h; g_feats_l[i*64+k]=l;
    }
}

// ---------------- kNN ----------------
__global__ void knn_k()
{
    __shared__ float sd[N_ALL];
    __shared__ float rv[8];
    __shared__ int   ri[8];
    int i = blockIdx.x;
    int tid = threadIdx.x;
    float xi0 = g_x[i*3+0], xi1 = g_x[i*3+1], xi2 = g_x[i*3+2];
    for (int j = tid; j < N_ALL; j += 256) {
        float dx = xi0 - g_x[j*3+0];
        float dy = xi1 - g_x[j*3+1];
        float dz = xi2 - g_x[j*3+2];
        float d2 = dx*dx + dy*dy + dz*dz;
        sd[j] = (j == i) ? __int_as_float(0x7f800000) : d2;
    }
    __syncthreads();
    int lane = tid & 31, warp = tid >> 5;
    for (int kk = 0; kk < KNN; kk++) {
        float best = __int_as_float(0x7f800000);
        int bi = 0x7fffffff;
        for (int j = tid; j < N_ALL; j += 256) {
            float v = sd[j];
            if (v < best) { best = v; bi = j; }
        }
        #pragma unroll
        for (int o = 16; o; o >>= 1) {
            float ov = __shfl_xor_sync(0xffffffff, best, o);
            int   oi = __shfl_xor_sync(0xffffffff, bi, o);
            if (ov < best || (ov == best && oi < bi)) { best = ov; bi = oi; }
        }
        if (lane == 0) { rv[warp] = best; ri[warp] = bi; }
        __syncthreads();
        if (tid == 0) {
            float b = rv[0]; int idx = ri[0];
            #pragma unroll
            for (int w = 1; w < 8; w++) {
                if (rv[w] < b || (rv[w] == b && ri[w] < idx)) { b = rv[w]; idx = ri[w]; }
            }
            g_col[i*KNN + kk] = idx;
            sd[idx] = __int_as_float(0x7f800000);
        }
        __syncthreads();
    }
}

// ---------------- emb0 ----------------
__global__ void emb0_k()
{
    int e = blockIdx.x*blockDim.x + threadIdx.x;
    if (e >= NEDGE) return;
    int r = e / KNN, c = g_col[e];
    float dx = g_x[r*3+0]-g_x[c*3+0];
    float dy = g_x[r*3+1]-g_x[c*3+1];
    float dz = g_x[r*3+2]-g_x[c*3+2];
    float d2 = dx*dx + dy*dy + dz*dz;
    float d = sqrtf(d2 + 1e-8f);
    #pragma unroll
    for (int j=0;j<6;j++) {
        float a = d * c_freqs[j];
        g_emb0[e*12+j]   = sinf(a);
        g_emb0[e*12+6+j] = cosf(a);
    }
}

// ---------------- per-layer geometry ----------------
__global__ void geom_k()
{
    int e = blockIdx.x*blockDim.x + threadIdx.x;
    if (e >= NEDGE) return;
    int r = e / KNN, c = g_col[e];
    float dx = g_x[r*3+0]-g_x[c*3+0];
    float dy = g_x[r*3+1]-g_x[c*3+1];
    float dz = g_x[r*3+2]-g_x[c*3+2];
    float d2 = dx*dx + dy*dy + dz*dz;
    float den = sqrtf(d2 + 1e-8f);
    float inv = 1.f / (den + 1.f);
    g_cdiff[e*3+0] = dx*inv;
    g_cdiff[e*3+1] = dy*inv;
    g_cdiff[e*3+2] = dz*inv;
    float ea[32];
    #pragma unroll
    for (int j=0;j<6;j++) {
        float a = den * c_freqs[j];
        ea[j]   = sinf(a);
        ea[6+j] = cosf(a);
    }
    #pragma unroll
    for (int j=0;j<12;j++) ea[12+j] = g_emb0[e*12+j];
    #pragma unroll
    for (int j=24;j<32;j++) ea[j] = 0.f;
    #pragma unroll
    for (int j=0;j<32;j++) {
        bf16 h,l; split2(ea[j], h, l);
        g_ea_h[e*32+j]=h; g_ea_l[e*32+j]=l;
    }
}

// ================= pipelined tensor-core GEMM (ldmatrix frag loads) =================
// mode 0: dense A; mode 1: edge cat; mode 2: node cat
// epi 0: plain store (outF / outHi+outLo)
// epi 1: store outF + partOut[gm*2+by] = sum_half(v * gvec)
// epi 2: no store; partOut[gm*2+by] = sum_half(v * gvec)
#define BM 128
#define BN 128
#define BK 32
#define ASTR 40
#define TILE_E (BM*ASTR)
#define STAGE_E (4*TILE_E)
#define SMEM_BYTES (2*STAGE_E*2)  // 81920

__device__ __forceinline__ void cp16(void* smem, const void* g, int sz) {
    uint32_t s = (uint32_t)__cvta_generic_to_shared(smem);
    asm volatile("cp.async.cg.shared.global [%0], [%1], 16, %2;\n"
                 :: "r"(s), "l"(g), "r"(sz) : "memory");
}
__device__ __forceinline__ void cp_commit() {
    asm volatile("cp.async.commit_group;\n" ::: "memory");
}
__device__ __forceinline__ void cp_wait1() {
    asm volatile("cp.async.wait_group 1;\n" ::: "memory");
}
__device__ __forceinline__ void cp_wait0() {
    asm volatile("cp.async.wait_group 0;\n" ::: "memory");
}

__device__ __forceinline__ void mma16816(float* d, const unsigned* a, const unsigned* b)
{
    asm volatile(
        "mma.sync.aligned.m16n8k16.row.col.f32.bf16.bf16.f32 "
        "{%0,%1,%2,%3}, {%4,%5,%6,%7}, {%8,%9}, {%0,%1,%2,%3};\n"
        : "+f"(d[0]), "+f"(d[1]), "+f"(d[2]), "+f"(d[3])
        : "r"(a[0]), "r"(a[1]), "r"(a[2]), "r"(a[3]), "r"(b[0]), "r"(b[1]));
}

__device__ __forceinline__ void ldsm_x4(unsigned* r, const bf16* p)
{
    uint32_t a = (uint32_t)__cvta_generic_to_shared(p);
    asm volatile("ldmatrix.sync.aligned.m8n8.x4.shared.b16 {%0,%1,%2,%3}, [%4];\n"
                 : "=r"(r[0]), "=r"(r[1]), "=r"(r[2]), "=r"(r[3]) : "r"(a));
}

__global__ void __launch_bounds__(256, 2)
mma_gemm_k(const bf16* __restrict__ Ahi, const bf16* __restrict__ Alo, int lda,
           const int* __restrict__ colIdx,
           const bf16* __restrict__ eaHi, const bf16* __restrict__ eaLo,
           const bf16* __restrict__ agHi, const bf16* __restrict__ agLo,
           const bf16* __restrict__ Whi, const bf16* __restrict__ Wlo, int ldw,
           const float* __restrict__ bias, const float* __restrict__ resid,
           float* __restrict__ outF, bf16* __restrict__ outHi, bf16* __restrict__ outLo,
           const float* __restrict__ gvec, float* __restrict__ partOut,
           int Kdim, int mode, int act, int epi)
{
    extern __shared__ bf16 dsm[];
    __shared__ int   sOff1[BM];
    __shared__ int   sOff2[BM];
    __shared__ float s_gvec[BN];
    __shared__ float s_part[BM][2];

    int tid  = threadIdx.x;
    int lane = tid & 31, warp = tid >> 5;
    int wm = warp & 3, wn = warp >> 2;          // 4x2 warps, warp tile 32x64
    int m0 = blockIdx.x * BM, n0 = blockIdx.y * BN;
    int g = lane >> 2, t = lane & 3;
    int lrow = lane & 15;                       // ldmatrix row within 16-row tile pair
    int lcol = (lane >> 4) * 8;                 // ldmatrix k-half select

    if (mode != 0 && tid < BM) {
        int gm = m0 + tid;
        if (mode == 1) { sOff1[tid] = (gm/KNN)*HID; sOff2[tid] = colIdx[gm]*HID; }
        else           { sOff1[tid] = gm*HID; sOff2[tid] = (gm < N_LIG) ? gm*HID : -1; }
    }
    if (epi != 0 && tid < BN) s_gvec[tid] = gvec[n0 + tid];
    __syncthreads();

    float acc[2][8][4];
    #pragma unroll
    for (int i=0;i<2;i++)
        #pragma unroll
        for (int j=0;j<8;j++)
            #pragma unroll
            for (int r=0;r<4;r++) acc[i][j][r] = 0.f;

    int ktiles = Kdim >> 5;

    auto load_tile = [&](int kt, int s) {
        int k0 = kt * BK;
        bf16* base = dsm + s*STAGE_E;
        #pragma unroll
        for (int i = 0; i < 2; i++) {
            int c = tid + i*256;
            int m = c >> 2, kc = (c & 3)*8;
            int gk = k0 + kc;
            const bf16 *sH, *sL; int sz = 16;
            if (mode == 0) {
                sH = Ahi + (size_t)(m0+m)*lda + gk;
                sL = Alo + (size_t)(m0+m)*lda + gk;
            } else if (mode == 1) {
                if (gk < 256)      { sH = Ahi + sOff1[m] + gk;       sL = Alo + sOff1[m] + gk; }
                else if (gk < 512) { sH = Ahi + sOff2[m] + gk-256;   sL = Alo + sOff2[m] + gk-256; }
                else               { int o = (m0+m)*32 + gk-512;     sH = eaHi + o; sL = eaLo + o; }
            } else {
                if (gk < 256)      { sH = Ahi + sOff1[m] + gk;       sL = Alo + sOff1[m] + gk; }
                else {
                    int o = sOff2[m];
                    if (o < 0) { sz = 0; o = 0; }
                    sH = agHi + o + gk-256; sL = agLo + o + gk-256;
                }
            }
            cp16(base + m*ASTR + kc, sH, sz);
            cp16(base + TILE_E + m*ASTR + kc, sL, sz);
        }
        #pragma unroll
        for (int i = 0; i < 2; i++) {
            int c = tid + i*256;
            int n = c >> 2, kc = (c & 3)*8;
            int gk = k0 + kc;
            cp16(base + 2*TILE_E + n*ASTR + kc, Whi + (size_t)(n0+n)*ldw + gk, 16);
            cp16(base + 3*TILE_E + n*ASTR + kc, Wlo + (size_t)(n0+n)*ldw + gk, 16);
        }
    };

    load_tile(0, 0);
    cp_commit();

    int buf = 0;
    for (int kt = 0; kt < ktiles; kt++) {
        if (kt+1 < ktiles) { load_tile(kt+1, buf^1); cp_commit(); cp_wait1(); }
        else               { cp_wait0(); }
        __syncthreads();

        const bf16* AsH = dsm + buf*STAGE_E;
        const bf16* AsL = AsH + TILE_E;
        const bf16* BsH = AsH + 2*TILE_E;
        const bf16* BsL = AsH + 3*TILE_E;

        #pragma unroll
        for (int ks = 0; ks < BK; ks += 16) {
            // A frags: ldmatrix.x4 per (i, hi/lo). Tile order matches mma A frag:
            // r0=(rows0-7,k0-7) r1=(rows8-15,k0-7) r2=(rows0-7,k8-15) r3=(rows8-15,k8-15)
            unsigned afh[2][4], afl[2][4];
            #pragma unroll
            for (int i=0;i<2;i++) {
                int ar = (wm*32 + i*16 + lrow)*ASTR + ks + lcol;
                ldsm_x4(afh[i], AsH + ar);
                ldsm_x4(afl[i], AsL + ar);
            }
            // B frags: ldmatrix.x4 per (j-pair, hi/lo):
            // r0=b0 of j=2jp, r1=b0 of j=2jp+1, r2=b1 of j=2jp, r3=b1 of j=2jp+1
            unsigned bfh[8][2], bfl[8][2];
            #pragma unroll
            for (int jp=0;jp<4;jp++) {
                int br = (wn*64 + jp*16 + lrow)*ASTR + ks + lcol;
                unsigned rh[4], rl[4];
                ldsm_x4(rh, BsH + br);
                ldsm_x4(rl, BsL + br);
                bfh[2*jp  ][0]=rh[0]; bfh[2*jp  ][1]=rh[2];
                bfh[2*jp+1][0]=rh[1]; bfh[2*jp+1][1]=rh[3];
                bfl[2*jp  ][0]=rl[0]; bfl[2*jp  ][1]=rl[2];
                bfl[2*jp+1][0]=rl[1]; bfl[2*jp+1][1]=rl[3];
            }
            #pragma unroll
            for (int j=0;j<8;j++)
                #pragma unroll
                for (int i=0;i<2;i++) {
                    mma16816(acc[i][j], afh[i], bfh[j]);
                    mma16816(acc[i][j], afh[i], bfl[j]);
                    mma16816(acc[i][j], afl[i], bfh[j]);
                }
        }
        __syncthreads();
        buf ^= 1;
    }

    // ---- epilogue ----
    float part[2][2] = {{0.f,0.f},{0.f,0.f}};
    #pragma unroll
    for (int i=0;i<2;i++) {
        #pragma unroll
        for (int j=0;j<8;j++) {
            int lc = wn*64 + j*8 + t*2;          // local col in [0,BN)
            int cn = n0 + lc;
            float b0 = bias[cn], b1 = bias[cn+1];
            #pragma unroll
            for (int r=0;r<2;r++) {
                int gm = m0 + wm*32 + i*16 + g + r*8;
                size_t off = (size_t)gm*HID + cn;
                float v0 = acc[i][j][r*2+0] + b0;
                float v1 = acc[i][j][r*2+1] + b1;
                if (resid) { v0 += resid[off]; v1 += resid[off+1]; }
                if (act == 1) {
                    v0 = v0 / (1.f + expf(-v0));
                    v1 = v1 / (1.f + expf(-v1));
                }
                if (epi != 0) part[i][r] += v0*s_gvec[lc] + v1*s_gvec[lc+1];
                if (epi != 2) {
                    if (outF) *reinterpret_cast<float2*>(&outF[off]) = make_float2(v0, v1);
                    if (outHi) {
                        bf16 h0,l0,h1,l1;
                        split2(v0, h0, l0); split2(v1, h1, l1);
                        *reinterpret_cast<__nv_bfloat162*>(&outHi[off]) = __nv_bfloat162(h0, h1);
                        *reinterpret_cast<__nv_bfloat162*>(&outLo[off]) = __nv_bfloat162(l0, l1);
                    }
                }
            }
        }
    }

    if (epi != 0) {
        #pragma unroll
        for (int i=0;i<2;i++)
            #pragma unroll
            for (int r=0;r<2;r++) {
                float p = part[i][r];
                p += __shfl_xor_sync(0xffffffff, p, 1);
                p += __shfl_xor_sync(0xffffffff, p, 2);
                if (t == 0) s_part[wm*32 + i*16 + g + r*8][wn] = p;
            }
        __syncthreads();
        if (wn == 0 && t == 0) {
            #pragma unroll
            for (int i=0;i<2;i++)
                #pragma unroll
                for (int r=0;r<2;r++) {
                    int rl = wm*32 + i*16 + g + r*8;
                    partOut[(size_t)(m0 + rl)*2 + blockIdx.y] = s_part[rl][0] + s_part[rl][1];
                }
        }
    }
}

// ---------------- segment sum with fused attention gate -> split agg ----------------
__global__ void agg_k(const float* __restrict__ ab)
{
    __shared__ float sg[KNN];
    int i = blockIdx.x;
    int c = threadIdx.x;
    if (c < KNN) {
        int e = i*KNN + c;
        float d = g_part[e*2] + g_part[e*2+1] + ab[0];
        sg[c] = 1.f / (1.f + expf(-d));
    }
    __syncthreads();
    float acc = 0.f;
    int base = i * KNN;
    #pragma unroll
    for (int k = 0; k < KNN; k++) acc += g_m2[(base+k)*HID + c] * sg[k];
    acc *= 0.2f;
    bf16 h,l; split2(acc, h, l);
    g_agg_h[i*HID + c] = h;
    g_agg_l[i*HID + c] = l;
}

// ---------------- coordinate update ----------------
__global__ void xupd_k()
{
    int idx = blockIdx.x*blockDim.x + threadIdx.x;
    if (idx >= N_LIG*3) return;
    int i = idx / 3, d = idx % 3;
    float acc = 0.f;
    int base = i * KNN;
    #pragma unroll
    for (int k = 0; k < KNN; k++) {
        int e = base + k;
        float s = g_spart[e*2] + g_spart[e*2+1];
        acc += g_cdiff[e*3 + d] * s;
    }
    g_x[i*3 + d] += acc * 0.2f;
}

// ---------------- output ----------------
__global__ void out_k(const float* __restrict__ wout, const float* __restrict__ bout,
                      const float* __restrict__ posw, float* __restrict__ out)
{
    __shared__ float sh[HID];
    int i = blockIdx.x;
    int tid = threadIdx.x;
    for (int k = tid; k < HID; k += 32) sh[k] = g_h[i*HID + k];
    __syncthreads();
    float acc = bout[tid];
    #pragma unroll 8
    for (int k = 0; k < HID; k++) acc += sh[k] * wout[k*FEAT + tid];
    out[N_LIG*3 + i*FEAT + tid] = acc;
    if (tid < 3) out[i*3 + tid] = g_x[i*3 + tid] * posw[0];
}

// ---------------- launch ----------------
extern "C" void kernel_launch(void* const* d_in, const int* in_sizes, int n_in,
                              void* d_out, int out_size)
{
    const float* protein_positions = (const float*)d_in[0];
    const int*   protein_ele       = (const int*)  d_in[1];
    const int*   protein_aa        = (const int*)  d_in[2];
    const int*   protein_bb        = (const int*)  d_in[3];
    const float* Xt_pos            = (const float*)d_in[4];
    const float* Xt_features       = (const float*)d_in[5];
    const int*   t_in              = (const int*)  d_in[6];
    const float* Wt_time           = (const float*)d_in[7];
    const float* W_ele             = (const float*)d_in[8];
    const float* W_aa              = (const float*)d_in[9];
    const float* W_bb              = (const float*)d_in[10];
    const float* W_in              = (const float*)d_in[11];
    const float* b_in              = (const float*)d_in[12];
    const float* W_out             = (const float*)d_in[13];
    const float* b_out             = (const float*)d_in[14];
    const float* edge_W1           = (const float*)d_in[15];
    const float* edge_b1           = (const float*)d_in[16];
    const float* edge_W2           = (const float*)d_in[17];
    const float* edge_b2           = (const float*)d_in[18];
    const float* att_W             = (const float*)d_in[19];
    const float* att_b             = (const float*)d_in[20];
    const float* node_W1           = (const float*)d_in[21];
    const float* node_b1           = (const float*)d_in[22];
    const float* node_W2           = (const float*)d_in[23];
    const float* node_b2           = (const float*)d_in[24];
    const float* coord_W1          = (const float*)d_in[25];
    const float* coord_b1          = (const float*)d_in[26];
    const float* coord_W2          = (const float*)d_in[27];
    const float* coord_b2          = (const float*)d_in[28];
    const float* coord_W3          = (const float*)d_in[29];
    const float* pos_w             = (const float*)d_in[30];

    cudaFuncSetAttribute(mma_gemm_k, cudaFuncAttributeMaxDynamicSharedMemorySize, SMEM_BYTES);

    float *p_h, *p_m2, *p_part, *p_spart;
    int *p_col;
    bf16 *p_fh, *p_fl, *p_hh, *p_hl, *p_uh, *p_ul, *p_agh, *p_agl, *p_eah, *p_eal, *p_m1h, *p_m1l;
    bf16 *p_we1h,*p_we1l,*p_we2h,*p_we2l,*p_wn1h,*p_wn1l,*p_wn2h,*p_wn2l,*p_wc1h,*p_wc1l,*p_wc2h,*p_wc2l,*p_winh,*p_winl;
    cudaGetSymbolAddress((void**)&p_h,    g_h);
    cudaGetSymbolAddress((void**)&p_m2,   g_m2);
    cudaGetSymbolAddress((void**)&p_part, g_part);
    cudaGetSymbolAddress((void**)&p_spart,g_spart);
    cudaGetSymbolAddress((void**)&p_col,  g_col);
    cudaGetSymbolAddress((void**)&p_fh,  g_feats_h);  cudaGetSymbolAddress((void**)&p_fl,  g_feats_l);
    cudaGetSymbolAddress((void**)&p_hh,  g_h_h);      cudaGetSymbolAddress((void**)&p_hl,  g_h_l);
    cudaGetSymbolAddress((void**)&p_uh,  g_u_h);      cudaGetSymbolAddress((void**)&p_ul,  g_u_l);
    cudaGetSymbolAddress((void**)&p_agh, g_agg_h);    cudaGetSymbolAddress((void**)&p_agl, g_agg_l);
    cudaGetSymbolAddress((void**)&p_eah, g_ea_h);     cudaGetSymbolAddress((void**)&p_eal, g_ea_l);
    cudaGetSymbolAddress((void**)&p_m1h, g_m1_h);     cudaGetSymbolAddress((void**)&p_m1l, g_m1_l);
    cudaGetSymbolAddress((void**)&p_we1h,g_we1_h);    cudaGetSymbolAddress((void**)&p_we1l,g_we1_l);
    cudaGetSymbolAddress((void**)&p_we2h,g_we2_h);    cudaGetSymbolAddress((void**)&p_we2l,g_we2_l);
    cudaGetSymbolAddress((void**)&p_wn1h,g_wn1_h);    cudaGetSymbolAddress((void**)&p_wn1l,g_wn1_l);
    cudaGetSymbolAddress((void**)&p_wn2h,g_wn2_h);    cudaGetSymbolAddress((void**)&p_wn2l,g_wn2_l);
    cudaGetSymbolAddress((void**)&p_wc1h,g_wc1_h);    cudaGetSymbolAddress((void**)&p_wc1l,g_wc1_l);
    cudaGetSymbolAddress((void**)&p_wc2h,g_wc2_h);    cudaGetSymbolAddress((void**)&p_wc2l,g_wc2_l);
    cudaGetSymbolAddress((void**)&p_winh,g_win_h);    cudaGetSymbolAddress((void**)&p_winl,g_win_l);

    {
        int tot;
        tot = 1*HID*64;        wsplit_k<<<(tot+255)/256,256>>>(W_in,     p_winh, p_winl, 40,  HID, 64,  tot);
        tot = DEPTH*HID*544;   wsplit_k<<<(tot+255)/256,256>>>(edge_W1,  p_we1h, p_we1l, 536, HID, 544, tot);
        tot = DEPTH*HID*256;   wsplit_k<<<(tot+255)/256,256>>>(edge_W2,  p_we2h, p_we2l, 256, HID, 256, tot);
        tot = DEPTH*HID*512;   wsplit_k<<<(tot+255)/256,256>>>(node_W1,  p_wn1h, p_wn1l, 512, HID, 512, tot);
        tot = DEPTH*HID*256;   wsplit_k<<<(tot+255)/256,256>>>(node_W2,  p_wn2h, p_wn2l, 256, HID, 256, tot);
        tot = DEPTH*HID*544;   wsplit_k<<<(tot+255)/256,256>>>(coord_W1, p_wc1h, p_wc1l, 536, HID, 544, tot);
        tot = DEPTH*HID*256;   wsplit_k<<<(tot+255)/256,256>>>(coord_W2, p_wc2h, p_wc2l, 256, HID, 256, tot);
    }

    embed_k<<<(N_ALL+255)/256, 256>>>(protein_positions, protein_ele, protein_aa,
                                      protein_bb, Xt_pos, Xt_features, t_in, Wt_time,
                                      W_ele, W_aa, W_bb);
    knn_k<<<N_LIG, 256>>>();
    emb0_k<<<(NEDGE+255)/256, 256>>>();

    dim3 gEdge(NEDGE/BM, HID/BN);
    dim3 gNode(N_ALL/BM, HID/BN);

    // h = feats @ W_in + b_in
    mma_gemm_k<<<gNode, 256, SMEM_BYTES>>>(p_fh, p_fl, 64, nullptr, nullptr, nullptr,
                                           nullptr, nullptr, p_winh, p_winl, 64,
                                           b_in, nullptr, p_h, p_hh, p_hl,
                                           nullptr, nullptr, 64, 0, 0, 0);

    for (int l = 0; l < DEPTH; l++) {
        const bf16* we1h = p_we1h + (size_t)l*HID*544; const bf16* we1l = p_we1l + (size_t)l*HID*544;
        const bf16* we2h = p_we2h + (size_t)l*HID*256; const bf16* we2l = p_we2l + (size_t)l*HID*256;
        const bf16* wn1h = p_wn1h + (size_t)l*HID*512; const bf16* wn1l = p_wn1l + (size_t)l*HID*512;
        const bf16* wn2h = p_wn2h + (size_t)l*HID*256; const bf16* wn2l = p_wn2l + (size_t)l*HID*256;
        const bf16* wc1h = p_wc1h + (size_t)l*HID*544; const bf16* wc1l = p_wc1l + (size_t)l*HID*544;
        const bf16* wc2h = p_wc2h + (size_t)l*HID*256; const bf16* wc2l = p_wc2l + (size_t)l*HID*256;
        const float* eb1 = edge_b1 + l*HID;
        const float* eb2 = edge_b2 + l*HID;
        const float* aW  = att_W   + (size_t)l*HID;
        const float* ab  = att_b   + l;
        const float* nb1 = node_b1 + l*HID;
        const float* nb2 = node_b2 + l*HID;
        const float* cb1 = coord_b1 + l*HID;
        const float* cb2 = coord_b2 + l*HID;
        const float* cW3 = coord_W3 + (size_t)l*HID;

        geom_k<<<(NEDGE+255)/256, 256>>>();

        // m1 = silu(cat @ edge_W1 + b1) -> split
        mma_gemm_k<<<gEdge, 256, SMEM_BYTES>>>(p_hh, p_hl, 0, p_col, p_eah, p_eal,
                                               nullptr, nullptr, we1h, we1l, 544,
                                               eb1, nullptr, nullptr, p_m1h, p_m1l,
                                               nullptr, nullptr, 544, 1, 1, 0);
        // m2(un-gated) = silu(m1 @ edge_W2 + b2) -> fp32 + att partial dots
        mma_gemm_k<<<gEdge, 256, SMEM_BYTES>>>(p_m1h, p_m1l, HID, nullptr, nullptr, nullptr,
                                               nullptr, nullptr, we2h, we2l, 256,
                                               eb2, nullptr, p_m2, nullptr, nullptr,
                                               aW, p_part, 256, 0, 1, 1);
        // agg with fused gate
        agg_k<<<N_LIG, HID>>>(ab);
        // u = silu(cat(h, agg|0) @ node_W1 + b1) -> split
        mma_gemm_k<<<gNode, 256, SMEM_BYTES>>>(p_hh, p_hl, 0, nullptr, nullptr, nullptr,
                                               p_agh, p_agl, wn1h, wn1l, 512,
                                               nb1, nullptr, nullptr, p_uh, p_ul,
                                               nullptr, nullptr, 512, 2, 1, 0);
        // h = h + u @ node_W2 + b2 -> fp32 + split
        mma_gemm_k<<<gNode, 256, SMEM_BYTES>>>(p_uh, p_ul, HID, nullptr, nullptr, nullptr,
                                               nullptr, nullptr, wn2h, wn2l, 256,
                                               nb2, p_h, p_h, p_hh, p_hl,
                                               nullptr, nullptr, 256, 0, 0, 0);
        // c1 = silu(cat @ coord_W1 + b1) -> split
        mma_gemm_k<<<gEdge, 256, SMEM_BYTES>>>(p_hh, p_hl, 0, p_col, p_eah, p_eal,
                                               nullptr, nullptr, wc1h, wc1l, 544,
                                               cb1, nullptr, nullptr, p_m1h, p_m1l,
                                               nullptr, nullptr, 544, 1, 1, 0);
        // coord scalar partials: silu(c1 @ coord_W2 + b2) . W3 -> spart only
        mma_gemm_k<<<gEdge, 256, SMEM_BYTES>>>(p_m1h, p_m1l, HID, nullptr, nullptr, nullptr,
                                               nullptr, nullptr, wc2h, wc2l, 256,
                                               cb2, nullptr, nullptr, nullptr, nullptr,
                                               cW3, p_spart, 256, 0, 1, 2);
        xupd_k<<<(N_LIG*3+255)/256, 256>>>();
    }

    out_k<<<N_LIG, 32>>>(W_out, b_out, pos_w, (float*)d_out);
}

// round 16
// speedup vs baseline: 1.3299x; 1.3299x over previous
#include <cuda_runtime.h>
#include <cuda_fp16.h>
#include <cstdint>
#include <math.h>

// Problem constants
#define N_LIG 1024
#define N_PROT 8192
#define N_ALL 9216
#define KNN 48
#define NEDGE (N_LIG*KNN)          // 49152
#define HID 256
#define FEAT 32
#define DEPTH 5
#define FIN 40

__constant__ float c_freqs[6] = {
    0.4188790204786391f, 1.6755160819145564f, 6.702064327658226f,
    26.808257310632902f, 107.23302924253161f, 428.93211697012644f
};

typedef __half fp16;

// ---------------- device scratch ----------------
__device__ float g_x[N_ALL*3];
__device__ float g_h[N_ALL*HID];
__device__ float g_m2[NEDGE*HID];
__device__ int   g_col[NEDGE];
__device__ float g_emb0[NEDGE*12];
__device__ float g_cdiff[NEDGE*3];
__device__ float g_part[NEDGE*2];    // att-gate partial dots (2 halves)
__device__ float g_spart[NEDGE*2];   // coord-scalar partial dots (2 halves)

// fp16 activations (single precision level)
__device__ fp16 g_feats16[N_ALL*64];
__device__ fp16 g_h16[N_ALL*HID];
__device__ fp16 g_u16[N_ALL*HID];
__device__ fp16 g_agg16[N_LIG*HID];
__device__ fp16 g_ea16[NEDGE*32];
__device__ fp16 g_m116[NEDGE*HID];
// transposed split weights [layer][N][ldw], fp16 hi/lo
__device__ fp16 g_we1_h[DEPTH*HID*544], g_we1_l[DEPTH*HID*544];
__device__ fp16 g_we2_h[DEPTH*HID*256], g_we2_l[DEPTH*HID*256];
__device__ fp16 g_wn1_h[DEPTH*HID*512], g_wn1_l[DEPTH*HID*512];
__device__ fp16 g_wn2_h[DEPTH*HID*256], g_wn2_l[DEPTH*HID*256];
__device__ fp16 g_wc1_h[DEPTH*HID*544], g_wc1_l[DEPTH*HID*544];
__device__ fp16 g_wc2_h[DEPTH*HID*256], g_wc2_l[DEPTH*HID*256];
__device__ fp16 g_win_h[HID*64],        g_win_l[HID*64];

// ---------------- weight convert+transpose+split ----------------
__global__ void wsplit_k(const float* __restrict__ W, fp16* __restrict__ hi,
                         fp16* __restrict__ lo, int K, int N, int ldw, int total)
{
    int idx = blockIdx.x*blockDim.x + threadIdx.x;
    if (idx >= total) return;
    int k = idx % ldw;
    int rem = idx / ldw;
    int n = rem % N;
    int l = rem / N;
    float v = (k < K) ? W[((size_t)l*K + k)*N + n] : 0.f;
    fp16 h = __float2half_rn(v);
    hi[idx] = h;
    lo[idx] = __float2half_rn(v - __half2float(h));
}

// ---------------- embed ----------------
__global__ void embed_k(const float* __restrict__ pp, const int* __restrict__ pe,
                        const int* __restrict__ pa, const int* __restrict__ pb,
                        const float* __restrict__ xt, const float* __restrict__ xf,
                        const int* __restrict__ tt, const float* __restrict__ wt,
                        const float* __restrict__ we, const float* __restrict__ wa,
                        const float* __restrict__ wb)
{
    int i = blockIdx.x*blockDim.x + threadIdx.x;
    if (i >= N_ALL) return;
    float f[64];
    #pragma unroll
    for (int k=0;k<64;k++) f[k]=0.f;
    if (i < N_LIG) {
        #pragma unroll
        for (int k=0;k<32;k++) f[k] = xf[i*32+k];
        int t = tt[i];
        #pragma unroll
        for (int k=0;k<8;k++) f[32+k] = wt[t*8+k];
        g_x[i*3+0]=xt[i*3+0]; g_x[i*3+1]=xt[i*3+1]; g_x[i*3+2]=xt[i*3+2];
    } else {
        int p = i - N_LIG;
        int e = pe[p], a = pa[p], b = pb[p];
        #pragma unroll
        for (int k=0;k<16;k++) f[k]    = we[e*16+k];
        #pragma unroll
        for (int k=0;k<16;k++) f[16+k] = wa[a*16+k];
        #pragma unroll
        for (int k=0;k<8;k++)  f[32+k] = wb[b*8+k];
        g_x[i*3+0]=pp[p*3+0]; g_x[i*3+1]=pp[p*3+1]; g_x[i*3+2]=pp[p*3+2];
    }
    #pragma unroll
    for (int k=0;k<64;k++) g_feats16[i*64+k] = __float2half_rn(f[k]);
}

// ---------------- kNN ----------------
__global__ void knn_k()
{
    __shared__ float sd[N_ALL];
    __shared__ float rv[8];
    __shared__ int   ri[8];
    int i = blockIdx.x;
    int tid = threadIdx.x;
    float xi0 = g_x[i*3+0], xi1 = g_x[i*3+1], xi2 = g_x[i*3+2];
    for (int j = tid; j < N_ALL; j += 256) {
        float dx = xi0 - g_x[j*3+0];
        float dy = xi1 - g_x[j*3+1];
        float dz = xi2 - g_x[j*3+2];
        float d2 = dx*dx + dy*dy + dz*dz;
        sd[j] = (j == i) ? __int_as_float(0x7f800000) : d2;
    }
    __syncthreads();
    int lane = tid & 31, warp = tid >> 5;
    for (int kk = 0; kk < KNN; kk++) {
        float best = __int_as_float(0x7f800000);
        int bi = 0x7fffffff;
        for (int j = tid; j < N_ALL; j += 256) {
            float v = sd[j];
            if (v < best) { best = v; bi = j; }
        }
        #pragma unroll
        for (int o = 16; o; o >>= 1) {
            float ov = __shfl_xor_sync(0xffffffff, best, o);
            int   oi = __shfl_xor_sync(0xffffffff, bi, o);
            if (ov < best || (ov == best && oi < bi)) { best = ov; bi = oi; }
        }
        if (lane == 0) { rv[warp] = best; ri[warp] = bi; }
        __syncthreads();
        if (tid == 0) {
            float b = rv[0]; int idx = ri[0];
            #pragma unroll
            for (int w = 1; w < 8; w++) {
                if (rv[w] < b || (rv[w] == b && ri[w] < idx)) { b = rv[w]; idx = ri[w]; }
            }
            g_col[i*KNN + kk] = idx;
            sd[idx] = __int_as_float(0x7f800000);
        }
        __syncthreads();
    }
}

// ---------------- emb0 ----------------
__global__ void emb0_k()
{
    int e = blockIdx.x*blockDim.x + threadIdx.x;
    if (e >= NEDGE) return;
    int r = e / KNN, c = g_col[e];
    float dx = g_x[r*3+0]-g_x[c*3+0];
    float dy = g_x[r*3+1]-g_x[c*3+1];
    float dz = g_x[r*3+2]-g_x[c*3+2];
    float d2 = dx*dx + dy*dy + dz*dz;
    float d = sqrtf(d2 + 1e-8f);
    #pragma unroll
    for (int j=0;j<6;j++) {
        float a = d * c_freqs[j];
        g_emb0[e*12+j]   = sinf(a);
        g_emb0[e*12+6+j] = cosf(a);
    }
}

// ---------------- per-layer geometry ----------------
__global__ void geom_k()
{
    int e = blockIdx.x*blockDim.x + threadIdx.x;
    if (e >= NEDGE) return;
    int r = e / KNN, c = g_col[e];
    float dx = g_x[r*3+0]-g_x[c*3+0];
    float dy = g_x[r*3+1]-g_x[c*3+1];
    float dz = g_x[r*3+2]-g_x[c*3+2];
    float d2 = dx*dx + dy*dy + dz*dz;
    float den = sqrtf(d2 + 1e-8f);
    float inv = 1.f / (den + 1.f);
    g_cdiff[e*3+0] = dx*inv;
    g_cdiff[e*3+1] = dy*inv;
    g_cdiff[e*3+2] = dz*inv;
    float ea[32];
    #pragma unroll
    for (int j=0;j<6;j++) {
        float a = den * c_freqs[j];
        ea[j]   = sinf(a);
        ea[6+j] = cosf(a);
    }
    #pragma unroll
    for (int j=0;j<12;j++) ea[12+j] = g_emb0[e*12+j];
    #pragma unroll
    for (int j=24;j<32;j++) ea[j] = 0.f;
    #pragma unroll
    for (int j=0;j<32;j++) g_ea16[e*32+j] = __float2half_rn(ea[j]);
}

// ============ pipelined fp16 tensor-core GEMM: a * (Whi + Wlo), 2 MMAs ============
// mode 0: dense A; mode 1: edge cat (K=544); mode 2: node cat (K=512)
// epi 0: plain store (outF / outH)
// epi 1: store outF + partOut[gm*2+by] = sum_half(v * gvec)
// epi 2: no store; partOut[gm*2+by] = sum_half(v * gvec)
#define BM 128
#define BN 128
#define BK 32
#define ASTR 40
#define TILE_E (BM*ASTR)          // 5120 halfs
#define STAGE_E (3*TILE_E)        // As, BsH, BsL
#define SMEM_BYTES (2*STAGE_E*2)  // 61440 B

__device__ __forceinline__ void cp16(void* smem, const void* g, int sz) {
    uint32_t s = (uint32_t)__cvta_generic_to_shared(smem);
    asm volatile("cp.async.cg.shared.global [%0], [%1], 16, %2;\n"
                 :: "r"(s), "l"(g), "r"(sz) : "memory");
}
__device__ __forceinline__ void cp_commit() {
    asm volatile("cp.async.commit_group;\n" ::: "memory");
}
__device__ __forceinline__ void cp_wait1() {
    asm volatile("cp.async.wait_group 1;\n" ::: "memory");
}
__device__ __forceinline__ void cp_wait0() {
    asm volatile("cp.async.wait_group 0;\n" ::: "memory");
}

__device__ __forceinline__ void mma16816(float* d, const unsigned* a, const unsigned* b)
{
    asm volatile(
        "mma.sync.aligned.m16n8k16.row.col.f32.f16.f16.f32 "
        "{%0,%1,%2,%3}, {%4,%5,%6,%7}, {%8,%9}, {%0,%1,%2,%3};\n"
        : "+f"(d[0]), "+f"(d[1]), "+f"(d[2]), "+f"(d[3])
        : "r"(a[0]), "r"(a[1]), "r"(a[2]), "r"(a[3]), "r"(b[0]), "r"(b[1]));
}

__global__ void __launch_bounds__(256, 2)
mma_gemm_k(const fp16* __restrict__ A, int lda,
           const int* __restrict__ colIdx,
           const fp16* __restrict__ ea, const fp16* __restrict__ ag,
           const fp16* __restrict__ Whi, const fp16* __restrict__ Wlo, int ldw,
           const float* __restrict__ bias, const float* __restrict__ resid,
           float* __restrict__ outF, fp16* __restrict__ outH,
           const float* __restrict__ gvec, float* __restrict__ partOut,
           int Kdim, int mode, int act, int epi)
{
    extern __shared__ fp16 dsm[];
    __shared__ int   sOff1[BM];
    __shared__ int   sOff2[BM];
    __shared__ float s_gvec[BN];
    __shared__ float s_part[BM][2];

    int tid  = threadIdx.x;
    int lane = tid & 31, warp = tid >> 5;
    int wm = warp & 3, wn = warp >> 2;          // 4x2 warps, warp tile 32x64
    int m0 = blockIdx.x * BM, n0 = blockIdx.y * BN;
    int g = lane >> 2, t = lane & 3;

    if (mode != 0 && tid < BM) {
        int gm = m0 + tid;
        if (mode == 1) { sOff1[tid] = (gm/KNN)*HID; sOff2[tid] = colIdx[gm]*HID; }
        else           { sOff1[tid] = gm*HID; sOff2[tid] = (gm < N_LIG) ? gm*HID : -1; }
    }
    if (epi != 0 && tid < BN) s_gvec[tid] = gvec[n0 + tid];
    __syncthreads();

    float acc[2][8][4];
    #pragma unroll
    for (int i=0;i<2;i++)
        #pragma unroll
        for (int j=0;j<8;j++)
            #pragma unroll
            for (int r=0;r<4;r++) acc[i][j][r] = 0.f;

    int ktiles = Kdim >> 5;

    auto load_tile = [&](int kt, int s) {
        int k0 = kt * BK;
        fp16* base = dsm + s*STAGE_E;
        // A: 512 chunks of 16B (single precision level)
        #pragma unroll
        for (int i = 0; i < 2; i++) {
            int c = tid + i*256;
            int m = c >> 2, kc = (c & 3)*8;
            int gk = k0 + kc;
            const fp16 *sA; int sz = 16;
            if (mode == 0) {
                sA = A + (size_t)(m0+m)*lda + gk;
            } else if (mode == 1) {
                if (gk < 256)      sA = A + sOff1[m] + gk;
                else if (gk < 512) sA = A + sOff2[m] + gk-256;
                else               sA = ea + (size_t)(m0+m)*32 + gk-512;
            } else {
                if (gk < 256)      sA = A + sOff1[m] + gk;
                else {
                    int o = sOff2[m];
                    if (o < 0) { sz = 0; o = 0; }
                    sA = ag + o + gk-256;
                }
            }
            cp16(base + m*ASTR + kc, sA, sz);
        }
        // B: 512 chunks each for hi and lo
        #pragma unroll
        for (int i = 0; i < 2; i++) {
            int c = tid + i*256;
            int n = c >> 2, kc = (c & 3)*8;
            int gk = k0 + kc;
            cp16(base + TILE_E   + n*ASTR + kc, Whi + (size_t)(n0+n)*ldw + gk, 16);
            cp16(base + 2*TILE_E + n*ASTR + kc, Wlo + (size_t)(n0+n)*ldw + gk, 16);
        }
    };

    load_tile(0, 0);
    cp_commit();

    int buf = 0;
    for (int kt = 0; kt < ktiles; kt++) {
        if (kt+1 < ktiles) { load_tile(kt+1, buf^1); cp_commit(); cp_wait1(); }
        else               { cp_wait0(); }
        __syncthreads();

        const fp16* As  = dsm + buf*STAGE_E;
        const fp16* BsH = As + TILE_E;
        const fp16* BsL = As + 2*TILE_E;

        #pragma unroll
        for (int ks = 0; ks < BK; ks += 16) {
            unsigned af[2][4];
            #pragma unroll
            for (int i=0;i<2;i++) {
                int row = wm*32 + i*16 + g;
                af[i][0] = *reinterpret_cast<const unsigned*>(&As[(row  )*ASTR + ks + t*2]);
                af[i][1] = *reinterpret_cast<const unsigned*>(&As[(row+8)*ASTR + ks + t*2]);
                af[i][2] = *reinterpret_cast<const unsigned*>(&As[(row  )*ASTR + ks + 8 + t*2]);
                af[i][3] = *reinterpret_cast<const unsigned*>(&As[(row+8)*ASTR + ks + 8 + t*2]);
            }
            #pragma unroll
            for (int j=0;j<8;j++) {
                int n = wn*64 + j*8 + g;
                unsigned bh[2], bl[2];
                bh[0] = *reinterpret_cast<const unsigned*>(&BsH[n*ASTR + ks + t*2]);
                bh[1] = *reinterpret_cast<const unsigned*>(&BsH[n*ASTR + ks + 8 + t*2]);
                bl[0] = *reinterpret_cast<const unsigned*>(&BsL[n*ASTR + ks + t*2]);
                bl[1] = *reinterpret_cast<const unsigned*>(&BsL[n*ASTR + ks + 8 + t*2]);
                #pragma unroll
                for (int i=0;i<2;i++) {
                    mma16816(acc[i][j], af[i], bh);
                    mma16816(acc[i][j], af[i], bl);
                }
            }
        }
        __syncthreads();
        buf ^= 1;
    }

    // ---- epilogue ----
    float part[2][2] = {{0.f,0.f},{0.f,0.f}};
    #pragma unroll
    for (int i=0;i<2;i++) {
        #pragma unroll
        for (int j=0;j<8;j++) {
            int lc = wn*64 + j*8 + t*2;
            int cn = n0 + lc;
            float b0 = bias[cn], b1 = bias[cn+1];
            #pragma unroll
            for (int r=0;r<2;r++) {
                int gm = m0 + wm*32 + i*16 + g + r*8;
                size_t off = (size_t)gm*HID + cn;
                float v0 = acc[i][j][r*2+0] + b0;
                float v1 = acc[i][j][r*2+1] + b1;
                if (resid) { v0 += resid[off]; v1 += resid[off+1]; }
                if (act == 1) {
                    v0 = v0 / (1.f + expf(-v0));
                    v1 = v1 / (1.f + expf(-v1));
                }
                if (epi != 0) part[i][r] += v0*s_gvec[lc] + v1*s_gvec[lc+1];
                if (epi != 2) {
                    if (outF) *reinterpret_cast<float2*>(&outF[off]) = make_float2(v0, v1);
                    if (outH) {
                        __half2 hv = __floats2half2_rn(v0, v1);
                        *reinterpret_cast<__half2*>(&outH[off]) = hv;
                    }
                }
            }
        }
    }

    if (epi != 0) {
        #pragma unroll
        for (int i=0;i<2;i++)
            #pragma unroll
            for (int r=0;r<2;r++) {
                float p = part[i][r];
                p += __shfl_xor_sync(0xffffffff, p, 1);
                p += __shfl_xor_sync(0xffffffff, p, 2);
                if (t == 0) s_part[wm*32 + i*16 + g + r*8][wn] = p;
            }
        __syncthreads();
        if (wn == 0 && t == 0) {
            #pragma unroll
            for (int i=0;i<2;i++)
                #pragma unroll
                for (int r=0;r<2;r++) {
                    int rl = wm*32 + i*16 + g + r*8;
                    partOut[(size_t)(m0 + rl)*2 + blockIdx.y] = s_part[rl][0] + s_part[rl][1];
                }
        }
    }
}

// ---------------- segment sum with fused attention gate ----------------
__global__ void agg_k(const float* __restrict__ ab)
{
    __shared__ float sg[KNN];
    int i = blockIdx.x;
    int c = threadIdx.x;
    if (c < KNN) {
        int e = i*KNN + c;
        float d = g_part[e*2] + g_part[e*2+1] + ab[0];
        sg[c] = 1.f / (1.f + expf(-d));
    }
    __syncthreads();
    float acc = 0.f;
    int base = i * KNN;
    #pragma unroll
    for (int k = 0; k < KNN; k++) acc += g_m2[(base+k)*HID + c] * sg[k];
    acc *= 0.2f;
    g_agg16[i*HID + c] = __float2half_rn(acc);
}

// ---------------- coordinate update ----------------
__global__ void xupd_k()
{
    int idx = blockIdx.x*blockDim.x + threadIdx.x;
    if (idx >= N_LIG*3) return;
    int i = idx / 3, d = idx % 3;
    float acc = 0.f;
    int base = i * KNN;
    #pragma unroll
    for (int k = 0; k < KNN; k++) {
        int e = base + k;
        float s = g_spart[e*2] + g_spart[e*2+1];
        acc += g_cdiff[e*3 + d] * s;
    }
    g_x[i*3 + d] += acc * 0.2f;
}

// ---------------- output ----------------
__global__ void out_k(const float* __restrict__ wout, const float* __restrict__ bout,
                      const float* __restrict__ posw, float* __restrict__ out)
{
    __shared__ float sh[HID];
    int i = blockIdx.x;
    int tid = threadIdx.x;
    for (int k = tid; k < HID; k += 32) sh[k] = g_h[i*HID + k];
    __syncthreads();
    float acc = bout[tid];
    #pragma unroll 8
    for (int k = 0; k < HID; k++) acc += sh[k] * wout[k*FEAT + tid];
    out[N_LIG*3 + i*FEAT + tid] = acc;
    if (tid < 3) out[i*3 + tid] = g_x[i*3 + tid] * posw[0];
}

// ---------------- launch ----------------
extern "C" void kernel_launch(void* const* d_in, const int* in_sizes, int n_in,
                              void* d_out, int out_size)
{
    const float* protein_positions = (const float*)d_in[0];
    const int*   protein_ele       = (const int*)  d_in[1];
    const int*   protein_aa        = (const int*)  d_in[2];
    const int*   protein_bb        = (const int*)  d_in[3];
    const float* Xt_pos            = (const float*)d_in[4];
    const float* Xt_features       = (const float*)d_in[5];
    const int*   t_in              = (const int*)  d_in[6];
    const float* Wt_time           = (const float*)d_in[7];
    const float* W_ele             = (const float*)d_in[8];
    const float* W_aa              = (const float*)d_in[9];
    const float* W_bb              = (const float*)d_in[10];
    const float* W_in              = (const float*)d_in[11];
    const float* b_in              = (const float*)d_in[12];
    const float* W_out             = (const float*)d_in[13];
    const float* b_out             = (const float*)d_in[14];
    const float* edge_W1           = (const float*)d_in[15];
    const float* edge_b1           = (const float*)d_in[16];
    const float* edge_W2           = (const float*)d_in[17];
    const float* edge_b2           = (const float*)d_in[18];
    const float* att_W             = (const float*)d_in[19];
    const float* att_b             = (const float*)d_in[20];
    const float* node_W1           = (const float*)d_in[21];
    const float* node_b1           = (const float*)d_in[22];
    const float* node_W2           = (const float*)d_in[23];
    const float* node_b2           = (const float*)d_in[24];
    const float* coord_W1          = (const float*)d_in[25];
    const float* coord_b1          = (const float*)d_in[26];
    const float* coord_W2          = (const float*)d_in[27];
    const float* coord_b2          = (const float*)d_in[28];
    const float* coord_W3          = (const float*)d_in[29];
    const float* pos_w             = (const float*)d_in[30];

    cudaFuncSetAttribute(mma_gemm_k, cudaFuncAttributeMaxDynamicSharedMemorySize, SMEM_BYTES);

    float *p_h, *p_m2, *p_part, *p_spart;
    int *p_col;
    fp16 *p_f16, *p_h16, *p_u16, *p_ag16, *p_ea16, *p_m116;
    fp16 *p_we1h,*p_we1l,*p_we2h,*p_we2l,*p_wn1h,*p_wn1l,*p_wn2h,*p_wn2l,*p_wc1h,*p_wc1l,*p_wc2h,*p_wc2l,*p_winh,*p_winl;
    cudaGetSymbolAddress((void**)&p_h,    g_h);
    cudaGetSymbolAddress((void**)&p_m2,   g_m2);
    cudaGetSymbolAddress((void**)&p_part, g_part);
    cudaGetSymbolAddress((void**)&p_spart,g_spart);
    cudaGetSymbolAddress((void**)&p_col,  g_col);
    cudaGetSymbolAddress((void**)&p_f16,  g_feats16);
    cudaGetSymbolAddress((void**)&p_h16,  g_h16);
    cudaGetSymbolAddress((void**)&p_u16,  g_u16);
    cudaGetSymbolAddress((void**)&p_ag16, g_agg16);
    cudaGetSymbolAddress((void**)&p_ea16, g_ea16);
    cudaGetSymbolAddress((void**)&p_m116, g_m116);
    cudaGetSymbolAddress((void**)&p_we1h,g_we1_h);    cudaGetSymbolAddress((void**)&p_we1l,g_we1_l);
    cudaGetSymbolAddress((void**)&p_we2h,g_we2_h);    cudaGetSymbolAddress((void**)&p_we2l,g_we2_l);
    cudaGetSymbolAddress((void**)&p_wn1h,g_wn1_h);    cudaGetSymbolAddress((void**)&p_wn1l,g_wn1_l);
    cudaGetSymbolAddress((void**)&p_wn2h,g_wn2_h);    cudaGetSymbolAddress((void**)&p_wn2l,g_wn2_l);
    cudaGetSymbolAddress((void**)&p_wc1h,g_wc1_h);    cudaGetSymbolAddress((void**)&p_wc1l,g_wc1_l);
    cudaGetSymbolAddress((void**)&p_wc2h,g_wc2_h);    cudaGetSymbolAddress((void**)&p_wc2l,g_wc2_l);
    cudaGetSymbolAddress((void**)&p_winh,g_win_h);    cudaGetSymbolAddress((void**)&p_winl,g_win_l);

    {
        int tot;
        tot = 1*HID*64;        wsplit_k<<<(tot+255)/256,256>>>(W_in,     p_winh, p_winl, 40,  HID, 64,  tot);
        tot = DEPTH*HID*544;   wsplit_k<<<(tot+255)/256,256>>>(edge_W1,  p_we1h, p_we1l, 536, HID, 544, tot);
        tot = DEPTH*HID*256;   wsplit_k<<<(tot+255)/256,256>>>(edge_W2,  p_we2h, p_we2l, 256, HID, 256, tot);
        tot = DEPTH*HID*512;   wsplit_k<<<(tot+255)/256,256>>>(node_W1,  p_wn1h, p_wn1l, 512, HID, 512, tot);
        tot = DEPTH*HID*256;   wsplit_k<<<(tot+255)/256,256>>>(node_W2,  p_wn2h, p_wn2l, 256, HID, 256, tot);
        tot = DEPTH*HID*544;   wsplit_k<<<(tot+255)/256,256>>>(coord_W1, p_wc1h, p_wc1l, 536, HID, 544, tot);
        tot = DEPTH*HID*256;   wsplit_k<<<(tot+255)/256,256>>>(coord_W2, p_wc2h, p_wc2l, 256, HID, 256, tot);
    }

    embed_k<<<(N_ALL+255)/256, 256>>>(protein_positions, protein_ele, protein_aa,
                                      protein_bb, Xt_pos, Xt_features, t_in, Wt_time,
                                      W_ele, W_aa, W_bb);
    knn_k<<<N_LIG, 256>>>();
    emb0_k<<<(NEDGE+255)/256, 256>>>();

    dim3 gEdge(NEDGE/BM, HID/BN);
    dim3 gNode(N_ALL/BM, HID/BN);

    // h = feats @ W_in + b_in  -> fp32 + fp16
    mma_gemm_k<<<gNode, 256, SMEM_BYTES>>>(p_f16, 64, nullptr, nullptr, nullptr,
                                           p_winh, p_winl, 64,
                                           b_in, nullptr, p_h, p_h16,
                                           nullptr, nullptr, 64, 0, 0, 0);

    for (int l = 0; l < DEPTH; l++) {
        const fp16* we1h = p_we1h + (size_t)l*HID*544; const fp16* we1l = p_we1l + (size_t)l*HID*544;
        const fp16* we2h = p_we2h + (size_t)l*HID*256; const fp16* we2l = p_we2l + (size_t)l*HID*256;
        const fp16* wn1h = p_wn1h + (size_t)l*HID*512; const fp16* wn1l = p_wn1l + (size_t)l*HID*512;
        const fp16* wn2h = p_wn2h + (size_t)l*HID*256; const fp16* wn2l = p_wn2l + (size_t)l*HID*256;
        const fp16* wc1h = p_wc1h + (size_t)l*HID*544; const fp16* wc1l = p_wc1l + (size_t)l*HID*544;
        const fp16* wc2h = p_wc2h + (size_t)l*HID*256; const fp16* wc2l = p_wc2l + (size_t)l*HID*256;
        const float* eb1 = edge_b1 + l*HID;
        const float* eb2 = edge_b2 + l*HID;
        const float* aW  = att_W   + (size_t)l*HID;
        const float* ab  = att_b   + l;
        const float* nb1 = node_b1 + l*HID;
        const float* nb2 = node_b2 + l*HID;
        const float* cb1 = coord_b1 + l*HID;
        const float* cb2 = coord_b2 + l*HID;
        const float* cW3 = coord_W3 + (size_t)l*HID;

        geom_k<<<(NEDGE+255)/256, 256>>>();

        // m1 = silu(cat @ edge_W1 + b1) -> fp16
        mma_gemm_k<<<gEdge, 256, SMEM_BYTES>>>(p_h16, 0, p_col, p_ea16, nullptr,
                                               we1h, we1l, 544,
                                               eb1, nullptr, nullptr, p_m116,
                                               nullptr, nullptr, 544, 1, 1, 0);
        // m2(un-gated) = silu(m1 @ edge_W2 + b2) -> fp32 + att partial dots
        mma_gemm_k<<<gEdge, 256, SMEM_BYTES>>>(p_m116, HID, nullptr, nullptr, nullptr,
                                               we2h, we2l, 256,
                                               eb2, nullptr, p_m2, nullptr,
                                               aW, p_part, 256, 0, 1, 1);
        agg_k<<<N_LIG, HID>>>(ab);
        // u = silu(cat(h, agg|0) @ node_W1 + b1) -> fp16
        mma_gemm_k<<<gNode, 256, SMEM_BYTES>>>(p_h16, 0, nullptr, nullptr, p_ag16,
                                               wn1h, wn1l, 512,
                                               nb1, nullptr, nullptr, p_u16,
                                               nullptr, nullptr, 512, 2, 1, 0);
        // h = h + u @ node_W2 + b2 -> fp32 + fp16
        mma_gemm_k<<<gNode, 256, SMEM_BYTES>>>(p_u16, HID, nullptr, nullptr, nullptr,
                                               wn2h, wn2l, 256,
                                               nb2, p_h, p_h, p_h16,
                                               nullptr, nullptr, 256, 0, 0, 0);
        // c1 = silu(cat @ coord_W1 + b1) -> fp16
        mma_gemm_k<<<gEdge, 256, SMEM_BYTES>>>(p_h16, 0, p_col, p_ea16, nullptr,
                                               wc1h, wc1l, 544,
                                               cb1, nullptr, nullptr, p_m116,
                                               nullptr, nullptr, 544, 1, 1, 0);
        // coord scalar partials: silu(c1 @ coord_W2 + b2) . W3 -> spart only
        mma_gemm_k<<<gEdge, 256, SMEM_BYTES>>>(p_m116, HID, nullptr, nullptr, nullptr,
                                               wc2h, wc2l, 256,
                                               cb2, nullptr, nullptr, nullptr,
                                               cW3, p_spart, 256, 0, 1, 2);
        xupd_k<<<(N_LIG*3+255)/256, 256>>>();
    }

    out_k<<<N_LIG, 32>>>(W_out, b_out, pos_w, (float*)d_out);
}

// round 17
// speedup vs baseline: 1.6987x; 1.2773x over previous
#include <cuda_runtime.h>
#include <cuda_fp16.h>
#include <cstdint>
#include <math.h>

#define N_LIG 1024
#define N_PROT 8192
#define N_ALL 9216
#define KNN 48
#define NEDGE (N_LIG*KNN)
#define HID 256
#define FEAT 32
#define DEPTH 5
#define FIN 40

__constant__ float c_freqs[6] = {
    0.4188790204786391f, 1.6755160819145564f, 6.702064327658226f,
    26.808257310632902f, 107.23302924253161f, 428.93211697012644f
};

typedef __half fp16;

// ---------------- device scratch ----------------
__device__ float g_x[N_ALL*3];
__device__ float g_h[N_ALL*HID];
__device__ float g_m2[NEDGE*HID];
__device__ int   g_col[NEDGE];
__device__ float g_emb0[NEDGE*12];
__device__ float g_cdiff[NEDGE*3];
__device__ float g_eaf[NEDGE*24];
__device__ float g_part[NEDGE*2];
__device__ float g_spart[NEDGE*2];
__device__ float g_rowpart[N_LIG*HID];
__device__ float g_colpart[N_ALL*HID];
__device__ float g_zbias[HID];        // zero-initialized

__device__ fp16 g_feats16[N_ALL*64];
__device__ fp16 g_h16[N_ALL*HID];
__device__ fp16 g_u16[N_ALL*HID];
__device__ fp16 g_agg16[N_LIG*HID];
__device__ fp16 g_m116[NEDGE*HID];
__device__ fp16 g_we1a_h[DEPTH*HID*256], g_we1a_l[DEPTH*HID*256];
__device__ fp16 g_we1b_h[DEPTH*HID*256], g_we1b_l[DEPTH*HID*256];
__device__ fp16 g_we2_h[DEPTH*HID*256],  g_we2_l[DEPTH*HID*256];
__device__ fp16 g_wn1_h[DEPTH*HID*512],  g_wn1_l[DEPTH*HID*512];
__device__ fp16 g_wn2_h[DEPTH*HID*256],  g_wn2_l[DEPTH*HID*256];
__device__ fp16 g_wc1a_h[DEPTH*HID*256], g_wc1a_l[DEPTH*HID*256];
__device__ fp16 g_wc1b_h[DEPTH*HID*256], g_wc1b_l[DEPTH*HID*256];
__device__ fp16 g_wc2_h[DEPTH*HID*256],  g_wc2_l[DEPTH*HID*256];
__device__ fp16 g_win_h[HID*64],         g_win_l[HID*64];

// ---------------- weight convert+transpose+split (K-slice) ----------------
__global__ void wsplit_k(const float* __restrict__ W, fp16* __restrict__ hi,
                         fp16* __restrict__ lo, int k0, int K, int Ktot,
                         int N, int ldw, int total)
{
    int idx = blockIdx.x*blockDim.x + threadIdx.x;
    if (idx >= total) return;
    int k = idx % ldw;
    int rem = idx / ldw;
    int n = rem % N;
    int l = rem / N;
    float v = (k < K) ? W[((size_t)l*Ktot + k0 + k)*N + n] : 0.f;
    fp16 h = __float2half_rn(v);
    hi[idx] = h;
    lo[idx] = __float2half_rn(v - __half2float(h));
}

__global__ void zbias_k() { if (threadIdx.x < HID) g_zbias[threadIdx.x] = 0.f; }

// ---------------- embed ----------------
__global__ void embed_k(const float* __restrict__ pp, const int* __restrict__ pe,
                        const int* __restrict__ pa, const int* __restrict__ pb,
                        const float* __restrict__ xt, const float* __restrict__ xf,
                        const int* __restrict__ tt, const float* __restrict__ wt,
                        const float* __restrict__ we, const float* __restrict__ wa,
                        const float* __restrict__ wb)
{
    int i = blockIdx.x*blockDim.x + threadIdx.x;
    if (i >= N_ALL) return;
    float f[64];
    #pragma unroll
    for (int k=0;k<64;k++) f[k]=0.f;
    if (i < N_LIG) {
        #pragma unroll
        for (int k=0;k<32;k++) f[k] = xf[i*32+k];
        int t = tt[i];
        #pragma unroll
        for (int k=0;k<8;k++) f[32+k] = wt[t*8+k];
        g_x[i*3+0]=xt[i*3+0]; g_x[i*3+1]=xt[i*3+1]; g_x[i*3+2]=xt[i*3+2];
    } else {
        int p = i - N_LIG;
        int e = pe[p], a = pa[p], b = pb[p];
        #pragma unroll
        for (int k=0;k<16;k++) f[k]    = we[e*16+k];
        #pragma unroll
        for (int k=0;k<16;k++) f[16+k] = wa[a*16+k];
        #pragma unroll
        for (int k=0;k<8;k++)  f[32+k] = wb[b*8+k];
        g_x[i*3+0]=pp[p*3+0]; g_x[i*3+1]=pp[p*3+1]; g_x[i*3+2]=pp[p*3+2];
    }
    #pragma unroll
    for (int k=0;k<64;k++) g_feats16[i*64+k] = __float2half_rn(f[k]);
}

// ---------------- kNN ----------------
__global__ void knn_k()
{
    __shared__ float sd[N_ALL];
    __shared__ float rv[8];
    __shared__ int   ri[8];
    int i = blockIdx.x;
    int tid = threadIdx.x;
    float xi0 = g_x[i*3+0], xi1 = g_x[i*3+1], xi2 = g_x[i*3+2];
    for (int j = tid; j < N_ALL; j += 256) {
        float dx = xi0 - g_x[j*3+0];
        float dy = xi1 - g_x[j*3+1];
        float dz = xi2 - g_x[j*3+2];
        float d2 = dx*dx + dy*dy + dz*dz;
        sd[j] = (j == i) ? __int_as_float(0x7f800000) : d2;
    }
    __syncthreads();
    int lane = tid & 31, warp = tid >> 5;
    for (int kk = 0; kk < KNN; kk++) {
        float best = __int_as_float(0x7f800000);
        int bi = 0x7fffffff;
        for (int j = tid; j < N_ALL; j += 256) {
            float v = sd[j];
            if (v < best) { best = v; bi = j; }
        }
        #pragma unroll
        for (int o = 16; o; o >>= 1) {
            float ov = __shfl_xor_sync(0xffffffff, best, o);
            int   oi = __shfl_xor_sync(0xffffffff, bi, o);
            if (ov < best || (ov == best && oi < bi)) { best = ov; bi = oi; }
        }
        if (lane == 0) { rv[warp] = best; ri[warp] = bi; }
        __syncthreads();
        if (tid == 0) {
            float b = rv[0]; int idx = ri[0];
            #pragma unroll
            for (int w = 1; w < 8; w++) {
                if (rv[w] < b || (rv[w] == b && ri[w] < idx)) { b = rv[w]; idx = ri[w]; }
            }
            g_col[i*KNN + kk] = idx;
            sd[idx] = __int_as_float(0x7f800000);
        }
        __syncthreads();
    }
}

// ---------------- emb0 ----------------
__global__ void emb0_k()
{
    int e = blockIdx.x*blockDim.x + threadIdx.x;
    if (e >= NEDGE) return;
    int r = e / KNN, c = g_col[e];
    float dx = g_x[r*3+0]-g_x[c*3+0];
    float dy = g_x[r*3+1]-g_x[c*3+1];
    float dz = g_x[r*3+2]-g_x[c*3+2];
    float d2 = dx*dx + dy*dy + dz*dz;
    float d = sqrtf(d2 + 1e-8f);
    #pragma unroll
    for (int j=0;j<6;j++) {
        float a = d * c_freqs[j];
        g_emb0[e*12+j]   = sinf(a);
        g_emb0[e*12+6+j] = cosf(a);
    }
}

// ---------------- per-layer geometry ----------------
__global__ void geom_k()
{
    int e = blockIdx.x*blockDim.x + threadIdx.x;
    if (e >= NEDGE) return;
    int r = e / KNN, c = g_col[e];
    float dx = g_x[r*3+0]-g_x[c*3+0];
    float dy = g_x[r*3+1]-g_x[c*3+1];
    float dz = g_x[r*3+2]-g_x[c*3+2];
    float d2 = dx*dx + dy*dy + dz*dz;
    float den = sqrtf(d2 + 1e-8f);
    float inv = 1.f / (den + 1.f);
    g_cdiff[e*3+0] = dx*inv;
    g_cdiff[e*3+1] = dy*inv;
    g_cdiff[e*3+2] = dz*inv;
    #pragma unroll
    for (int j=0;j<6;j++) {
        float a = den * c_freqs[j];
        g_eaf[e*24+j]   = sinf(a);
        g_eaf[e*24+6+j] = cosf(a);
    }
    #pragma unroll
    for (int j=0;j<12;j++) g_eaf[e*24+12+j] = g_emb0[e*12+j];
}

// ---------------- edge assembly ----------------
__global__ void asm_k(const float* __restrict__ rowpart, const float* __restrict__ colpart,
                      const float* __restrict__ Wc, const float* __restrict__ bias,
                      fp16* __restrict__ out)
{
    __shared__ float sea[KNN*24];
    __shared__ int scol[KNN];
    int i = blockIdx.x, c = threadIdx.x;
    for (int t = c; t < KNN*24; t += 256) sea[t] = g_eaf[(size_t)i*KNN*24 + t];
    if (c < KNN) scol[c] = g_col[i*KNN + c];
    __syncthreads();
    float w[24];
    #pragma unroll
    for (int k=0;k<24;k++) w[k] = Wc[k*HID + c];
    float rp = rowpart[i*HID + c] + bias[c];
    #pragma unroll 4
    for (int e=0;e<KNN;e++) {
        float acc = rp + colpart[(size_t)scol[e]*HID + c];
        #pragma unroll
        for (int k=0;k<24;k++) acc += sea[e*24+k]*w[k];
        acc = acc/(1.f+expf(-acc));
        out[((size_t)(i*KNN+e))*HID + c] = __float2half_rn(acc);
    }
}

// ============ pipelined fp16 tensor-core GEMM: a * (Whi + Wlo), 2 MMAs ============
#define BM 128
#define BN 128
#define BK 32
#define ASTR 40
#define TILE_E (BM*ASTR)
#define STAGE_E (3*TILE_E)
#define SMEM_BYTES (2*STAGE_E*2)

__device__ __forceinline__ void cp16(void* smem, const void* g, int sz) {
    uint32_t s = (uint32_t)__cvta_generic_to_shared(smem);
    asm volatile("cp.async.cg.shared.global [%0], [%1], 16, %2;\n"
                 :: "r"(s), "l"(g), "r"(sz) : "memory");
}
__device__ __forceinline__ void cp_commit() {
    asm volatile("cp.async.commit_group;\n" ::: "memory");
}
__device__ __forceinline__ void cp_wait1() {
    asm volatile("cp.async.wait_group 1;\n" ::: "memory");
}
__device__ __forceinline__ void cp_wait0() {
    asm volatile("cp.async.wait_group 0;\n" ::: "memory");
}

__device__ __forceinline__ void mma16816(float* d, const unsigned* a, const unsigned* b)
{
    asm volatile(
        "mma.sync.aligned.m16n8k16.row.col.f32.f16.f16.f32 "
        "{%0,%1,%2,%3}, {%4,%5,%6,%7}, {%8,%9}, {%0,%1,%2,%3};\n"
        : "+f"(d[0]), "+f"(d[1]), "+f"(d[2]), "+f"(d[3])
        : "r"(a[0]), "r"(a[1]), "r"(a[2]), "r"(a[3]), "r"(b[0]), "r"(b[1]));
}

__global__ void __launch_bounds__(256, 2)
mma_gemm_k(const fp16* __restrict__ A, int lda,
           const fp16* __restrict__ ag,
           const fp16* __restrict__ Whi, const fp16* __restrict__ Wlo, int ldw,
           const float* __restrict__ bias, const float* __restrict__ resid,
           float* __restrict__ outF, fp16* __restrict__ outH,
           const float* __restrict__ gvec, float* __restrict__ partOut,
           int Kdim, int mode, int act, int epi)
{
    extern __shared__ fp16 dsm[];
    __shared__ int   sOff2[BM];
    __shared__ float s_gvec[BN];
    __shared__ float s_part[BM][2];

    int tid  = threadIdx.x;
    int lane = tid & 31, warp = tid >> 5;
    int wm = warp & 3, wn = warp >> 2;
    int m0 = blockIdx.x * BM, n0 = blockIdx.y * BN;
    int g = lane >> 2, t = lane & 3;

    if (mode == 2 && tid < BM) {
        int gm = m0 + tid;
        sOff2[tid] = (gm < N_LIG) ? gm*HID : -1;
    }
    if (epi != 0 && tid < BN) s_gvec[tid] = gvec[n0 + tid];
    __syncthreads();

    float acc[2][8][4];
    #pragma unroll
    for (int i=0;i<2;i++)
        #pragma unroll
        for (int j=0;j<8;j++)
            #pragma unroll
            for (int r=0;r<4;r++) acc[i][j][r] = 0.f;

    int ktiles = Kdim >> 5;

    auto load_tile = [&](int kt, int s) {
        int k0 = kt * BK;
        fp16* base = dsm + s*STAGE_E;
        #pragma unroll
        for (int i = 0; i < 2; i++) {
            int c = tid + i*256;
            int m = c >> 2, kc = (c & 3)*8;
            int gk = k0 + kc;
            const fp16 *sA; int sz = 16;
            if (mode == 0) {
                sA = A + (size_t)(m0+m)*lda + gk;
            } else {
                if (gk < 256)      sA = A + (size_t)(m0+m)*HID + gk;
                else {
                    int o = sOff2[m];
                    if (o < 0) { sz = 0; o = 0; }
                    sA = ag + o + gk-256;
                }
            }
            cp16(base + m*ASTR + kc, sA, sz);
        }
        #pragma unroll
        for (int i = 0; i < 2; i++) {
            int c = tid + i*256;
            int n = c >> 2, kc = (c & 3)*8;
            int gk = k0 + kc;
            cp16(base + TILE_E   + n*ASTR + kc, Whi + (size_t)(n0+n)*ldw + gk, 16);
            cp16(base + 2*TILE_E + n*ASTR + kc, Wlo + (size_t)(n0+n)*ldw + gk, 16);
        }
    };

    load_tile(0, 0);
    cp_commit();

    int buf = 0;
    for (int kt = 0; kt < ktiles; kt++) {
        if (kt+1 < ktiles) { load_tile(kt+1, buf^1); cp_commit(); cp_wait1(); }
        else               { cp_wait0(); }
        __syncthreads();

        const fp16* As  = dsm + buf*STAGE_E;
        const fp16* BsH = As + TILE_E;
        const fp16* BsL = As + 2*TILE_E;

        #pragma unroll
        for (int ks = 0; ks < BK; ks += 16) {
            unsigned af[2][4];
            #pragma unroll
            for (int i=0;i<2;i++) {
                int row = wm*32 + i*16 + g;
                af[i][0] = *reinterpret_cast<const unsigned*>(&As[(row  )*ASTR + ks + t*2]);
                af[i][1] = *reinterpret_cast<const unsigned*>(&As[(row+8)*ASTR + ks + t*2]);
                af[i][2] = *reinterpret_cast<const unsigned*>(&As[(row  )*ASTR + ks + 8 + t*2]);
                af[i][3] = *reinterpret_cast<const unsigned*>(&As[(row+8)*ASTR + ks + 8 + t*2]);
            }
            #pragma unroll
            for (int j=0;j<8;j++) {
                int n = wn*64 + j*8 + g;
                unsigned bh[2], bl[2];
                bh[0] = *reinterpret_cast<const unsigned*>(&BsH[n*ASTR + ks + t*2]);
                bh[1] = *reinterpret_cast<const unsigned*>(&BsH[n*ASTR + ks + 8 + t*2]);
                bl[0] = *reinterpret_cast<const unsigned*>(&BsL[n*ASTR + ks + t*2]);
                bl[1] = *reinterpret_cast<const unsigned*>(&BsL[n*ASTR + ks + 8 + t*2]);
                #pragma unroll
                for (int i=0;i<2;i++) {
                    mma16816(acc[i][j], af[i], bh);
                    mma16816(acc[i][j], af[i], bl);
                }
            }
        }
        __syncthreads();
        buf ^= 1;
    }

    float part[2][2] = {{0.f,0.f},{0.f,0.f}};
    #pragma unroll
    for (int i=0;i<2;i++) {
        #pragma unroll
        for (int j=0;j<8;j++) {
            int lc = wn*64 + j*8 + t*2;
            int cn = n0 + lc;
            float b0 = bias[cn], b1 = bias[cn+1];
            #pragma unroll
            for (int r=0;r<2;r++) {
                int gm = m0 + wm*32 + i*16 + g + r*8;
                size_t off = (size_t)gm*HID + cn;
                float v0 = acc[i][j][r*2+0] + b0;
                float v1 = acc[i][j][r*2+1] + b1;
                if (resid) { v0 += resid[off]; v1 += resid[off+1]; }
                if (act == 1) {
                    v0 = v0 / (1.f + expf(-v0));
                    v1 = v1 / (1.f + expf(-v1));
                }
                if (epi != 0) part[i][r] += v0*s_gvec[lc] + v1*s_gvec[lc+1];
                if (epi != 2) {
                    if (outF) *reinterpret_cast<float2*>(&outF[off]) = make_float2(v0, v1);
                    if (outH) {
                        __half2 hv = __floats2half2_rn(v0, v1);
                        *reinterpret_cast<__half2*>(&outH[off]) = hv;
                    }
                }
            }
        }
    }

    if (epi != 0) {
        #pragma unroll
        for (int i=0;i<2;i++)
            #pragma unroll
            for (int r=0;r<2;r++) {
                float p = part[i][r];
                p += __shfl_xor_sync(0xffffffff, p, 1);
                p += __shfl_xor_sync(0xffffffff, p, 2);
                if (t == 0) s_part[wm*32 + i*16 + g + r*8][wn] = p;
            }
        __syncthreads();
        if (wn == 0 && t == 0) {
            #pragma unroll
            for (int i=0;i<2;i++)
                #pragma unroll
                for (int r=0;r<2;r++) {
                    int rl = wm*32 + i*16 + g + r*8;
                    partOut[(size_t)(m0 + rl)*2 + blockIdx.y] = s_part[rl][0] + s_part[rl][1];
                }
        }
    }
}

// ---------------- segment sum with fused attention gate ----------------
__global__ void agg_k(const float* __restrict__ ab)
{
    __shared__ float sg[KNN];
    int i = blockIdx.x;
    int c = threadIdx.x;
    if (c < KNN) {
        int e = i*KNN + c;
        float d = g_part[e*2] + g_part[e*2+1] + ab[0];
        sg[c] = 1.f / (1.f + expf(-d));
    }
    __syncthreads();
    float acc = 0.f;
    int base = i * KNN;
    #pragma unroll
    for (int k = 0; k < KNN; k++) acc += g_m2[(base+k)*HID + c] * sg[k];
    acc *= 0.2f;
    g_agg16[i*HID + c] = __float2half_rn(acc);
}

// ---------------- coordinate update ----------------
__global__ void xupd_k()
{
    int idx = blockIdx.x*blockDim.x + threadIdx.x;
    if (idx >= N_LIG*3) return;
    int i = idx / 3, d = idx % 3;
    float acc = 0.f;
    int base = i * KNN;
    #pragma unroll
    for (int k = 0; k < KNN; k++) {
        int e = base + k;
        float s = g_spart[e*2] + g_spart[e*2+1];
        acc += g_cdiff[e*3 + d] * s;
    }
    g_x[i*3 + d] += acc * 0.2f;
}

// ---------------- output ----------------
__global__ void out_k(const float* __restrict__ wout, const float* __restrict__ bout,
                      const float* __restrict__ posw, float* __restrict__ out)
{
    __shared__ float sh[HID];
    int i = blockIdx.x;
    int tid = threadIdx.x;
    for (int k = tid; k < HID; k += 32) sh[k] = g_h[i*HID + k];
    __syncthreads();
    float acc = bout[tid];
    #pragma unroll 8
    for (int k = 0; k < HID; k++) acc += sh[k] * wout[k*FEAT + tid];
    out[N_LIG*3 + i*FEAT + tid] = acc;
    if (tid < 3) out[i*3 + tid] = g_x[i*3 + tid] * posw[0];
}

// ---------------- launch ----------------
extern "C" void kernel_launch(void* const* d_in, const int* in_sizes, int n_in,
                              void* d_out, int out_size)
{
    const float* protein_positions = (const float*)d_in[0];
    const int*   protein_ele       = (const int*)  d_in[1];
    const int*   protein_aa        = (const int*)  d_in[2];
    const int*   protein_bb        = (const int*)  d_in[3];
    const float* Xt_pos            = (const float*)d_in[4];
    const float* Xt_features       = (const float*)d_in[5];
    const int*   t_in              = (const int*)  d_in[6];
    const float* Wt_time           = (const float*)d_in[7];
    const float* W_ele             = (const float*)d_in[8];
    const float* W_aa              = (const float*)d_in[9];
    const float* W_bb              = (const float*)d_in[10];
    const float* W_in              = (const float*)d_in[11];
    const float* b_in              = (const float*)d_in[12];
    const float* W_out             = (const float*)d_in[13];
    const float* b_out             = (const float*)d_in[14];
    const float* edge_W1           = (const float*)d_in[15];
    const float* edge_b1           = (const float*)d_in[16];
    const float* edge_W2           = (const float*)d_in[17];
    const float* edge_b2           = (const float*)d_in[18];
    const float* att_W             = (const float*)d_in[19];
    const float* att_b             = (const float*)d_in[20];
    const float* node_W1           = (const float*)d_in[21];
    const float* node_b1           = (const float*)d_in[22];
    const float* node_W2           = (const float*)d_in[23];
    const float* node_b2           = (const float*)d_in[24];
    const float* coord_W1          = (const float*)d_in[25];
    const float* coord_b1          = (const float*)d_in[26];
    const float* coord_W2          = (const float*)d_in[27];
    const float* coord_b2          = (const float*)d_in[28];
    const float* coord_W3          = (const float*)d_in[29];
    const float* pos_w             = (const float*)d_in[30];

    cudaFuncSetAttribute(mma_gemm_k, cudaFuncAttributeMaxDynamicSharedMemorySize, SMEM_BYTES);

    float *p_h, *p_m2, *p_part, *p_spart, *p_rowp, *p_colp, *p_zb;
    fp16 *p_f16, *p_h16, *p_u16, *p_ag16, *p_m116;
    fp16 *p_we1ah,*p_we1al,*p_we1bh,*p_we1bl,*p_we2h,*p_we2l;
    fp16 *p_wn1h,*p_wn1l,*p_wn2h,*p_wn2l;
    fp16 *p_wc1ah,*p_wc1al,*p_wc1bh,*p_wc1bl,*p_wc2h,*p_wc2l,*p_winh,*p_winl;
    cudaGetSymbolAddress((void**)&p_h,    g_h);
    cudaGetSymbolAddress((void**)&p_m2,   g_m2);
    cudaGetSymbolAddress((void**)&p_part, g_part);
    cudaGetSymbolAddress((void**)&p_spart,g_spart);
    cudaGetSymbolAddress((void**)&p_rowp, g_rowpart);
    cudaGetSymbolAddress((void**)&p_colp, g_colpart);
    cudaGetSymbolAddress((void**)&p_zb,   g_zbias);
    cudaGetSymbolAddress((void**)&p_f16,  g_feats16);
    cudaGetSymbolAddress((void**)&p_h16,  g_h16);
    cudaGetSymbolAddress((void**)&p_u16,  g_u16);
    cudaGetSymbolAddress((void**)&p_ag16, g_agg16);
    cudaGetSymbolAddress((void**)&p_m116, g_m116);
    cudaGetSymbolAddress((void**)&p_we1ah,g_we1a_h);  cudaGetSymbolAddress((void**)&p_we1al,g_we1a_l);
    cudaGetSymbolAddress((void**)&p_we1bh,g_we1b_h);  cudaGetSymbolAddress((void**)&p_we1bl,g_we1b_l);
    cudaGetSymbolAddress((void**)&p_we2h, g_we2_h);   cudaGetSymbolAddress((void**)&p_we2l, g_we2_l);
    cudaGetSymbolAddress((void**)&p_wn1h, g_wn1_h);   cudaGetSymbolAddress((void**)&p_wn1l, g_wn1_l);
    cudaGetSymbolAddress((void**)&p_wn2h, g_wn2_h);   cudaGetSymbolAddress((void**)&p_wn2l, g_wn2_l);
    cudaGetSymbolAddress((void**)&p_wc1ah,g_wc1a_h);  cudaGetSymbolAddress((void**)&p_wc1al,g_wc1a_l);
    cudaGetSymbolAddress((void**)&p_wc1bh,g_wc1b_h);  cudaGetSymbolAddress((void**)&p_wc1bl,g_wc1b_l);
    cudaGetSymbolAddress((void**)&p_wc2h, g_wc2_h);   cudaGetSymbolAddress((void**)&p_wc2l, g_wc2_l);
    cudaGetSymbolAddress((void**)&p_winh, g_win_h);   cudaGetSymbolAddress((void**)&p_winl, g_win_l);

    zbias_k<<<1, 256>>>();
    {
        int tot;
        tot = 1*HID*64;       wsplit_k<<<(tot+255)/256,256>>>(W_in,     p_winh,  p_winl,  0,   40,  40,  HID, 64,  tot);
        tot = DEPTH*HID*256;  wsplit_k<<<(tot+255)/256,256>>>(edge_W1,  p_we1ah, p_we1al, 0,   256, 536, HID, 256, tot);
        tot = DEPTH*HID*256;  wsplit_k<<<(tot+255)/256,256>>>(edge_W1,  p_we1bh, p_we1bl, 256, 256, 536, HID, 256, tot);
        tot = DEPTH*HID*256;  wsplit_k<<<(tot+255)/256,256>>>(edge_W2,  p_we2h,  p_we2l,  0,   256, 256, HID, 256, tot);
        tot = DEPTH*HID*512;  wsplit_k<<<(tot+255)/256,256>>>(node_W1,  p_wn1h,  p_wn1l,  0,   512, 512, HID, 512, tot);
        tot = DEPTH*HID*256;  wsplit_k<<<(tot+255)/256,256>>>(node_W2,  p_wn2h,  p_wn2l,  0,   256, 256, HID, 256, tot);
        tot = DEPTH*HID*256;  wsplit_k<<<(tot+255)/256,256>>>(coord_W1, p_wc1ah, p_wc1al, 0,   256, 536, HID, 256, tot);
        tot = DEPTH*HID*256;  wsplit_k<<<(tot+255)/256,256>>>(coord_W1, p_wc1bh, p_wc1bl, 256, 256, 536, HID, 256, tot);
        tot = DEPTH*HID*256;  wsplit_k<<<(tot+255)/256,256>>>(coord_W2, p_wc2h,  p_wc2l,  0,   256, 256, HID, 256, tot);
    }

    embed_k<<<(N_ALL+255)/256, 256>>>(protein_positions, protein_ele, protein_aa,
                                      protein_bb, Xt_pos, Xt_features, t_in, Wt_time,
                                      W_ele, W_aa, W_bb);
    knn_k<<<N_LIG, 256>>>();
    emb0_k<<<(NEDGE+255)/256, 256>>>();

    dim3 gEdge(NEDGE/BM, HID/BN);
    dim3 gNode(N_ALL/BM, HID/BN);
    dim3 gRow(N_LIG/BM, HID/BN);

    // h = feats @ W_in + b_in  -> fp32 + fp16
    mma_gemm_k<<<gNode, 256, SMEM_BYTES>>>(p_f16, 64, nullptr,
                                           p_winh, p_winl, 64,
                                           b_in, nullptr, p_h, p_h16,
                                           nullptr, nullptr, 64, 0, 0, 0);

    for (int l = 0; l < DEPTH; l++) {
        const fp16* we1ah = p_we1ah + (size_t)l*HID*256; const fp16* we1al = p_we1al + (size_t)l*HID*256;
        const fp16* we1bh = p_we1bh + (size_t)l*HID*256; const fp16* we1bl = p_we1bl + (size_t)l*HID*256;
        const fp16* we2h  = p_we2h  + (size_t)l*HID*256; const fp16* we2l  = p_we2l  + (size_t)l*HID*256;
        const fp16* wn1h  = p_wn1h  + (size_t)l*HID*512; const fp16* wn1l  = p_wn1l  + (size_t)l*HID*512;
        const fp16* wn2h  = p_wn2h  + (size_t)l*HID*256; const fp16* wn2l  = p_wn2l  + (size_t)l*HID*256;
        const fp16* wc1ah = p_wc1ah + (size_t)l*HID*256; const fp16* wc1al = p_wc1al + (size_t)l*HID*256;
        const fp16* wc1bh = p_wc1bh + (size_t)l*HID*256; const fp16* wc1bl = p_wc1bl + (size_t)l*HID*256;
        const fp16* wc2h  = p_wc2h  + (size_t)l*HID*256; const fp16* wc2l  = p_wc2l  + (size_t)l*HID*256;
        const float* eWc = edge_W1  + (size_t)l*536*HID + (size_t)512*HID;
        const float* cWc = coord_W1 + (size_t)l*536*HID + (size_t)512*HID;
        const float* eb1 = edge_b1 + l*HID;
        const float* eb2 = edge_b2 + l*HID;
        const float* aW  = att_W   + (size_t)l*HID;
        const float* ab  = att_b   + l;
        const float* nb1 = node_b1 + l*HID;
        const float* nb2 = node_b2 + l*HID;
        const float* cb1 = coord_b1 + l*HID;
        const float* cb2 = coord_b2 + l*HID;
        const float* cW3 = coord_W3 + (size_t)l*HID;

        geom_k<<<(NEDGE+255)/256, 256>>>();

        // colpart = h @ W1b (zero bias, no act)
        mma_gemm_k<<<gNode, 256, SMEM_BYTES>>>(p_h16, HID, nullptr,
                                               we1bh, we1bl, 256,
                                               p_zb, nullptr, p_colp, nullptr,
                                               nullptr, nullptr, 256, 0, 0, 0);
        // rowpart = h[:1024] @ W1a (zero bias)
        mma_gemm_k<<<gRow, 256, SMEM_BYTES>>>(p_h16, HID, nullptr,
                                              we1ah, we1al, 256,
                                              p_zb, nullptr, p_rowp, nullptr,
                                              nullptr, nullptr, 256, 0, 0, 0);
        asm_k<<<N_LIG, 256>>>(p_rowp, p_colp, eWc, eb1, p_m116);

        // m2(un-gated) = silu(m1 @ edge_W2 + b2) -> fp32 + att partial dots
        mma_gemm_k<<<gEdge, 256, SMEM_BYTES>>>(p_m116, HID, nullptr,
                                               we2h, we2l, 256,
                                               eb2, nullptr, p_m2, nullptr,
                                               aW, p_part, 256, 0, 1, 1);
        agg_k<<<N_LIG, HID>>>(ab);
        // u = silu(cat(h, agg|0) @ node_W1 + b1) -> fp16
        mma_gemm_k<<<gNode, 256, SMEM_BYTES>>>(p_h16, 0, p_ag16,
                                               wn1h, wn1l, 512,
                                               nb1, nullptr, nullptr, p_u16,
                                               nullptr, nullptr, 512, 2, 1, 0);
        // h = h + u @ node_W2 + b2 -> fp32 + fp16
        mma_gemm_k<<<gNode, 256, SMEM_BYTES>>>(p_u16, HID, nullptr,
                                               wn2h, wn2l, 256,
                                               nb2, p_h, p_h, p_h16,
                                               nullptr, nullptr, 256, 0, 0, 0);
        // coord parts with NEW h
        mma_gemm_k<<<gNode, 256, SMEM_BYTES>>>(p_h16, HID, nullptr,
                                               wc1bh, wc1bl, 256,
                                               p_zb, nullptr, p_colp, nullptr,
                                               nullptr, nullptr, 256, 0, 0, 0);
        mma_gemm_k<<<gRow, 256, SMEM_BYTES>>>(p_h16, HID, nullptr,
                                              wc1ah, wc1al, 256,
                                              p_zb, nullptr, p_rowp, nullptr,
                                              nullptr, nullptr, 256, 0, 0, 0);
        asm_k<<<N_LIG, 256>>>(p_rowp, p_colp, cWc, cb1, p_m116);

        // coord scalar partials: silu(c1 @ coord_W2 + b2) . W3 -> spart only
        mma_gemm_k<<<gEdge, 256, SMEM_BYTES>>>(p_m116, HID, nullptr,
                                               wc2h, wc2l, 256,
                                               cb2, nullptr, nullptr, nullptr,
                                               cW3, p_spart, 256, 0, 1, 2);
        xupd_k<<<(N_LIG*3+255)/256, 256>>>();
    }

    out_k<<<N_LIG, 32>>>(W_out, b_out, pos_w, (float*)d_out);
}